// round 1
// baseline (speedup 1.0000x reference)
#include <cuda_runtime.h>
#include <cstdint>

// ---------------------------------------------------------------------------
// TFN: out = ((relu(relu(F@W1+b1)@W2+b2))@W3)+b3,  F = trilinear fusion
// F[b, (ai,vi,ti)] = a[b,ai]*v[b,vi]*t[b,ti],  a=[1,audio], v=[1,video], t=[1,text]
// B=256, A+1=33, V+1=33, T+1=129, K = 1089 chunks of 129, PF=128.
//
// Strategy: split-K tf32 tensor-core GEMM. Per (ai,vi) chunk:
//   P = T(256x129) @ Wc(129x128)   (tf32 mma, fp32 accum, zeroed per chunk)
//   acc[b,p] += s[b] * P[b,p]      (fp32 FMA; s[b]=a[b,ai]*v[b,vi])
// Grid 4 N-slices x 38 K-groups = 152 CTAs (one wave on GB300).
// ---------------------------------------------------------------------------

#define CHUNKS 1089
#define GSPLIT 38
#define TSTR   132            // T smem row stride (floats): banks (4r+c) conflict-free
#define WSTR   140            // W smem row stride (floats): conflict-free B-frag loads
#define TSM_FLOATS (256*TSTR + 8)      // + zero tail for k=132..135 overread at row 255
#define WSM_FLOATS (32*WSTR)
#define SMEM_BYTES ((TSM_FLOATS + WSM_FLOATS) * 4)

__device__ float g_T[257 * TSTR];          // tf32-rounded [1|text], rows pad to 132, row 256 = 0
__device__ float g_part[GSPLIT * 256 * 128];
__device__ float g_h1[256 * 128];

__device__ __forceinline__ uint32_t f2tf32(float f) {
    uint32_t u;
    asm("cvt.rna.tf32.f32 %0, %1;" : "=r"(u) : "f"(f));
    return u;
}

// ---------------------------------------------------------------------------
__global__ void prep_T(const float* __restrict__ text) {
    int b = blockIdx.x;       // 256
    int t = threadIdx.x;      // 132
    float v;
    if (t == 0)        v = 1.0f;
    else if (t <= 128) v = text[b * 128 + (t - 1)];
    else               v = 0.0f;
    g_T[b * TSTR + t] = __uint_as_float(f2tf32(v));
}

// ---------------------------------------------------------------------------
__global__ void __launch_bounds__(256, 1)
tfn_gemm(const float* __restrict__ audio, const float* __restrict__ video,
         const float* __restrict__ W1) {
    extern __shared__ float sm[];
    float* Tsm = sm;                       // TSM_FLOATS
    float* Wsm = sm + TSM_FLOATS;          // 32 x WSTR, layout [n][k] (transposed)

    const int tid   = threadIdx.x;
    const int slice = blockIdx.x;          // 0..3 : 32-wide N slice of PF=128
    const int g     = blockIdx.y;          // 0..GSPLIT-1 : K group

    // stage T into smem (vectorized), zero the small tail
    {
        const float4* src = (const float4*)g_T;
        float4* dst = (float4*)Tsm;
        #pragma unroll 4
        for (int i = tid; i < (256 * TSTR) / 4; i += 256) dst[i] = src[i];
        if (tid < 8) Tsm[256 * TSTR + tid] = 0.0f;
    }
    // zero W pad columns k = 129..139 (loads only touch k < 129)
    for (int i = tid; i < 32 * WSTR; i += 256)
        if ((i % WSTR) >= 129) Wsm[i] = 0.0f;

    const int warp  = tid >> 5;
    const int lane  = tid & 31;
    const int grp   = lane >> 2;           // 0..7
    const int tig   = lane & 3;            // 0..3
    const int mbase = warp << 5;           // each warp owns 32 batch rows

    float acc[2][4][4];
    #pragma unroll
    for (int mt = 0; mt < 2; mt++)
        #pragma unroll
        for (int nt = 0; nt < 4; nt++)
            #pragma unroll
            for (int e = 0; e < 4; e++) acc[mt][nt][e] = 0.0f;

    __syncthreads();

    for (int c = g; c < CHUNKS; c += GSPLIT) {
        const int ai = c / 33;
        const int vi = c - ai * 33;

        // per-row scales s = a[b,ai]*v[b,vi] for the 4 row-octets of this thread
        float s[4];
        #pragma unroll
        for (int r4 = 0; r4 < 4; r4++) {
            int row  = mbase + (r4 << 3) + grp;
            float av = (ai == 0) ? 1.0f : __ldg(&audio[row * 32 + ai - 1]);
            float vv = (vi == 0) ? 1.0f : __ldg(&video[row * 32 + vi - 1]);
            s[r4] = av * vv;
        }

        // load W chunk slice (129 x 32), transpose into Wsm[n][k], tf32-round
        __syncthreads();   // previous compute done before overwriting Wsm
        const float* Wg = W1 + (size_t)c * 129 * 128 + slice * 32;
        for (int i = tid; i < 129 * 8; i += 256) {
            int k  = i >> 3;
            int j4 = (i & 7) << 2;
            float4 w = *(const float4*)(Wg + (size_t)k * 128 + j4);
            Wsm[(j4 + 0) * WSTR + k] = __uint_as_float(f2tf32(w.x));
            Wsm[(j4 + 1) * WSTR + k] = __uint_as_float(f2tf32(w.y));
            Wsm[(j4 + 2) * WSTR + k] = __uint_as_float(f2tf32(w.z));
            Wsm[(j4 + 3) * WSTR + k] = __uint_as_float(f2tf32(w.w));
        }
        __syncthreads();

        // P = T @ Wc  (tf32 mma, fp32 accum), zeroed per chunk
        float tacc[2][4][4];
        #pragma unroll
        for (int mt = 0; mt < 2; mt++)
            #pragma unroll
            for (int nt = 0; nt < 4; nt++)
                #pragma unroll
                for (int e = 0; e < 4; e++) tacc[mt][nt][e] = 0.0f;

        #pragma unroll
        for (int kt = 0; kt < 17; kt++) {
            const int k0 = kt << 3;
            uint32_t a[2][4];
            #pragma unroll
            for (int mt = 0; mt < 2; mt++) {
                const int r0 = mbase + (mt << 4) + grp;
                a[mt][0] = __float_as_uint(Tsm[r0 * TSTR + k0 + tig]);
                a[mt][1] = __float_as_uint(Tsm[(r0 + 8) * TSTR + k0 + tig]);
                a[mt][2] = __float_as_uint(Tsm[r0 * TSTR + k0 + tig + 4]);
                a[mt][3] = __float_as_uint(Tsm[(r0 + 8) * TSTR + k0 + tig + 4]);
            }
            #pragma unroll
            for (int nt = 0; nt < 4; nt++) {
                uint32_t b0 = __float_as_uint(Wsm[((nt << 3) + grp) * WSTR + k0 + tig]);
                uint32_t b1 = __float_as_uint(Wsm[((nt << 3) + grp) * WSTR + k0 + tig + 4]);
                #pragma unroll
                for (int mt = 0; mt < 2; mt++) {
                    asm volatile(
                        "mma.sync.aligned.m16n8k8.row.col.f32.tf32.tf32.f32 "
                        "{%0,%1,%2,%3}, {%4,%5,%6,%7}, {%8,%9}, {%0,%1,%2,%3};"
                        : "+f"(tacc[mt][nt][0]), "+f"(tacc[mt][nt][1]),
                          "+f"(tacc[mt][nt][2]), "+f"(tacc[mt][nt][3])
                        : "r"(a[mt][0]), "r"(a[mt][1]), "r"(a[mt][2]), "r"(a[mt][3]),
                          "r"(b0), "r"(b1));
                }
            }
        }

        // acc += s[row] * P   (fp32)
        #pragma unroll
        for (int mt = 0; mt < 2; mt++)
            #pragma unroll
            for (int nt = 0; nt < 4; nt++) {
                acc[mt][nt][0] = fmaf(s[2 * mt],     tacc[mt][nt][0], acc[mt][nt][0]);
                acc[mt][nt][1] = fmaf(s[2 * mt],     tacc[mt][nt][1], acc[mt][nt][1]);
                acc[mt][nt][2] = fmaf(s[2 * mt + 1], tacc[mt][nt][2], acc[mt][nt][2]);
                acc[mt][nt][3] = fmaf(s[2 * mt + 1], tacc[mt][nt][3], acc[mt][nt][3]);
            }
    }

    // write split-K partials (no atomics; fully overwritten each replay)
    float* part = g_part + (size_t)g * (256 * 128);
    #pragma unroll
    for (int mt = 0; mt < 2; mt++) {
        int r0 = mbase + (mt << 4) + grp;
        #pragma unroll
        for (int nt = 0; nt < 4; nt++) {
            int col = (slice << 5) + (nt << 3) + (tig << 1);
            *(float2*)&part[r0 * 128 + col]       = make_float2(acc[mt][nt][0], acc[mt][nt][1]);
            *(float2*)&part[(r0 + 8) * 128 + col] = make_float2(acc[mt][nt][2], acc[mt][nt][3]);
        }
    }
}

// ---------------------------------------------------------------------------
__global__ void reduce_bias_relu(const float* __restrict__ b1) {
    int idx = blockIdx.x * 256 + threadIdx.x;   // grid 128 -> 32768 outputs
    float sum = b1[idx & 127];
    #pragma unroll
    for (int gg = 0; gg < GSPLIT; gg++) sum += g_part[gg * 32768 + idx];
    g_h1[idx] = fmaxf(sum, 0.0f);
}

// ---------------------------------------------------------------------------
__global__ void l2l3(const float* __restrict__ W2, const float* __restrict__ b2,
                     const float* __restrict__ W3, const float* __restrict__ b3,
                     float* __restrict__ out) {
    __shared__ float row[128];
    __shared__ float red[128];
    const int b = blockIdx.x;     // 256
    const int p = threadIdx.x;    // 128

    row[p] = g_h1[b * 128 + p];
    __syncthreads();

    float sum = b2[p];
    #pragma unroll 8
    for (int k = 0; k < 128; k++) sum = fmaf(row[k], W2[k * 128 + p], sum);
    float h2 = fmaxf(sum, 0.0f);

    red[p] = h2 * W3[p];
    __syncthreads();
    #pragma unroll
    for (int sft = 64; sft > 0; sft >>= 1) {
        if (p < sft) red[p] += red[p + sft];
        __syncthreads();
    }
    if (p == 0) out[b] = red[0] + b3[0];
}

// ---------------------------------------------------------------------------
extern "C" void kernel_launch(void* const* d_in, const int* in_sizes, int n_in,
                              void* d_out, int out_size) {
    (void)in_sizes; (void)n_in; (void)out_size;
    const float* audio = (const float*)d_in[0];
    const float* video = (const float*)d_in[1];
    const float* text  = (const float*)d_in[2];
    const float* W1    = (const float*)d_in[3];
    const float* b1    = (const float*)d_in[4];
    const float* W2    = (const float*)d_in[5];
    const float* b2    = (const float*)d_in[6];
    const float* W3    = (const float*)d_in[7];
    const float* b3    = (const float*)d_in[8];
    float* out = (float*)d_out;

    cudaFuncSetAttribute(tfn_gemm, cudaFuncAttributeMaxDynamicSharedMemorySize,
                         SMEM_BYTES);

    prep_T<<<256, 132>>>(text);
    dim3 grid(4, GSPLIT);
    tfn_gemm<<<grid, 256, SMEM_BYTES>>>(audio, video, W1);
    reduce_bias_relu<<<128, 256>>>(b1);
    l2l3<<<256, 128>>>(W2, b2, W3, b3, out);
}